// round 10
// baseline (speedup 1.0000x reference)
#include <cuda_runtime.h>
#include <math.h>

#define NN 100000
#define EE 3200000
#define HIDC 128

// ---------------- device scratch (no allocations allowed) ----------------
__device__ int   g_flag64;          // 1 if edge_index is int64, 0 if int32
__device__ int   g_deg[NN];
__device__ float g_dinv[NN];
__device__ int   g_rowptr[NN + 1];
__device__ int   g_cursor[NN];
__device__ int   g_src[EE];
__device__ float g_w[EE];
__device__ float g_h0[(size_t)NN * HIDC];
__device__ float g_bufA[(size_t)NN * HIDC];
__device__ float g_bufB[(size_t)NN * HIDC];
__device__ float g_sbuf[(size_t)NN * HIDC];

// ---------------- dtype detection ----------------
// int64 edge indices (< 2^31) have all-zero high words at odd positions.
// int32 edge indices have random node ids there -> effectively never all zero.
__global__ void detect_kernel(const int* __restrict__ ew) {
    if (threadIdx.x == 0) {
        int allzero = 1;
        for (int i = 0; i < 256; i++) {
            if (ew[2 * i + 1] != 0) { allzero = 0; break; }
        }
        g_flag64 = allzero;
    }
}

__device__ __forceinline__ int load_idx(const int* __restrict__ ew, long long elem, int f64) {
    return f64 ? ew[2 * elem] : ew[elem];   // little-endian low word
}

// ---------------- graph build ----------------
__global__ void count_kernel(const int* __restrict__ ew) {
    int e = blockIdx.x * blockDim.x + threadIdx.x;
    if (e < EE) {
        int f64 = g_flag64;
        int c = load_idx(ew, (long long)EE + e, f64);
        if ((unsigned)c < NN) atomicAdd(&g_deg[c], 1);
    }
}

// single-block exclusive scan over degrees -> rowptr, cursor, dinv
__global__ void scan_kernel() {
    __shared__ int sums[1024];
    const int T = 1024;
    int t = threadIdx.x;
    const int CH = (NN + T - 1) / T;  // 98
    int lo = t * CH;
    int hi = lo + CH;
    if (hi > NN) hi = NN;
    if (lo > NN) lo = NN;
    int s = 0;
    for (int i = lo; i < hi; i++) s += g_deg[i];
    sums[t] = s;
    __syncthreads();
    for (int off = 1; off < T; off <<= 1) {
        int v = (t >= off) ? sums[t - off] : 0;
        __syncthreads();
        sums[t] += v;
        __syncthreads();
    }
    int run = sums[t] - s;  // exclusive prefix of this chunk
    for (int i = lo; i < hi; i++) {
        int d = g_deg[i];
        g_rowptr[i] = run;
        g_cursor[i] = run;
        g_dinv[i]   = rsqrtf((float)(d + 1));  // +1 self loop
        run += d;
    }
    if (t == T - 1) g_rowptr[NN] = run;
}

__global__ void fill_kernel(const int* __restrict__ ew) {
    int e = blockIdx.x * blockDim.x + threadIdx.x;
    if (e < EE) {
        int f64 = g_flag64;
        int r = load_idx(ew, e, f64);
        int c = load_idx(ew, (long long)EE + e, f64);
        if ((unsigned)r < NN && (unsigned)c < NN) {
            int pos = atomicAdd(&g_cursor[c], 1);
            g_src[pos] = r;
            g_w[pos]   = g_dinv[r] * g_dinv[c];
        }
    }
}

// ---------------- SpMM + residual: s = 0.9*(A_norm h) + 0.1*h0 ----------------
__global__ __launch_bounds__(256) void spmm_kernel(const float* __restrict__ h,
                                                   const float* __restrict__ h0f,
                                                   float* __restrict__ sout) {
    int warp = (blockIdx.x * blockDim.x + threadIdx.x) >> 5;
    if (warp >= NN) return;
    int lane = threadIdx.x & 31;
    int beg = g_rowptr[warp];
    int end = g_rowptr[warp + 1];

    float4 acc = make_float4(0.f, 0.f, 0.f, 0.f);
    int e0 = beg;
    for (; e0 + 32 <= end; e0 += 32) {
        int   src = g_src[e0 + lane];
        float w   = g_w[e0 + lane];
#pragma unroll 8
        for (int j = 0; j < 32; j++) {
            int   sidx = __shfl_sync(0xffffffffu, src, j);
            float ww   = __shfl_sync(0xffffffffu, w, j);
            float4 hv = *(const float4*)(h + (size_t)sidx * HIDC + lane * 4);
            acc.x = fmaf(ww, hv.x, acc.x);
            acc.y = fmaf(ww, hv.y, acc.y);
            acc.z = fmaf(ww, hv.z, acc.z);
            acc.w = fmaf(ww, hv.w, acc.w);
        }
    }
    if (e0 < end) {
        int cnt = end - e0;
        int   src = 0;
        float w   = 0.f;
        if (lane < cnt) { src = g_src[e0 + lane]; w = g_w[e0 + lane]; }
        for (int j = 0; j < cnt; j++) {
            int   sidx = __shfl_sync(0xffffffffu, src, j);
            float ww   = __shfl_sync(0xffffffffu, w, j);
            float4 hv = *(const float4*)(h + (size_t)sidx * HIDC + lane * 4);
            acc.x = fmaf(ww, hv.x, acc.x);
            acc.y = fmaf(ww, hv.y, acc.y);
            acc.z = fmaf(ww, hv.z, acc.z);
            acc.w = fmaf(ww, hv.w, acc.w);
        }
    }
    // analytic self loop
    float di = g_dinv[warp];
    float ws = di * di;
    float4 hv = *(const float4*)(h + (size_t)warp * HIDC + lane * 4);
    acc.x = fmaf(ws, hv.x, acc.x);
    acc.y = fmaf(ws, hv.y, acc.y);
    acc.z = fmaf(ws, hv.z, acc.z);
    acc.w = fmaf(ws, hv.w, acc.w);

    float4 r0 = *(const float4*)(h0f + (size_t)warp * HIDC + lane * 4);
    float4 o;
    o.x = 0.9f * acc.x + 0.1f * r0.x;
    o.y = 0.9f * acc.y + 0.1f * r0.y;
    o.z = 0.9f * acc.z + 0.1f * r0.z;
    o.w = 0.9f * acc.w + 0.1f * r0.w;
    *(float4*)(sout + (size_t)warp * HIDC + lane * 4) = o;
}

// ---------------- GEMM: out = cs*S + cw*(S@W) (+bias) (relu?) ----------------
// Block: 32 rows x 128 cols, 256 threads; thread = 1 row x 16 strided cols.
__global__ __launch_bounds__(256) void gemm_kernel(const float* __restrict__ S,
                                                   const float* __restrict__ W,
                                                   const float* __restrict__ bias,
                                                   float cs, float cw, int relu,
                                                   float* __restrict__ out) {
    __shared__ float ss[32][132];   // pad 132: spread broadcasts, float4-aligned
    __shared__ float Ws[32][128];
    int tid = threadIdx.x;
    int row0 = blockIdx.x * 32;
    int rg = tid >> 3;   // 0..31 row in tile
    int cg = tid & 7;    // 0..7

    {
        const float4* Sv = (const float4*)(S + (size_t)row0 * HIDC);
#pragma unroll
        for (int i = 0; i < 4; i++) {
            int idx = tid + i * 256;
            int r = idx >> 5, c4 = idx & 31;
            float4 v = Sv[r * 32 + c4];
            *(float4*)&ss[r][c4 * 4] = v;
        }
    }

    float4 acc[4];
#pragma unroll
    for (int j = 0; j < 4; j++) acc[j] = make_float4(0.f, 0.f, 0.f, 0.f);

    for (int kc = 0; kc < 4; kc++) {
        __syncthreads();
        const float4* Wv = (const float4*)(W + (size_t)kc * 32 * HIDC);
#pragma unroll
        for (int i = 0; i < 4; i++) {
            int idx = tid + i * 256;
            int r = idx >> 5, c4 = idx & 31;
            *(float4*)&Ws[r][c4 * 4] = Wv[r * 32 + c4];
        }
        __syncthreads();
#pragma unroll
        for (int kk = 0; kk < 32; kk++) {
            float sv = ss[rg][kc * 32 + kk];
#pragma unroll
            for (int j = 0; j < 4; j++) {
                float4 w4 = *(const float4*)&Ws[kk][(cg + 8 * j) * 4];
                acc[j].x = fmaf(sv, w4.x, acc[j].x);
                acc[j].y = fmaf(sv, w4.y, acc[j].y);
                acc[j].z = fmaf(sv, w4.z, acc[j].z);
                acc[j].w = fmaf(sv, w4.w, acc[j].w);
            }
        }
    }

#pragma unroll
    for (int j = 0; j < 4; j++) {
        int col = (cg + 8 * j) * 4;
        float4 o = acc[j];
        o.x *= cw; o.y *= cw; o.z *= cw; o.w *= cw;
        if (cs != 0.f) {
            float4 sv = *(const float4*)&ss[rg][col];
            o.x = fmaf(cs, sv.x, o.x);
            o.y = fmaf(cs, sv.y, o.y);
            o.z = fmaf(cs, sv.z, o.z);
            o.w = fmaf(cs, sv.w, o.w);
        }
        if (bias) {
            float4 b = *(const float4*)(bias + col);
            o.x += b.x; o.y += b.y; o.z += b.z; o.w += b.w;
        }
        if (relu) {
            o.x = fmaxf(o.x, 0.f); o.y = fmaxf(o.y, 0.f);
            o.z = fmaxf(o.z, 0.f); o.w = fmaxf(o.w, 0.f);
        }
        *(float4*)(out + (size_t)(row0 + rg) * HIDC + col) = o;
    }
}

// ---------------- output projection: out[n] = h[n] . W_out + b_out ----------------
__global__ __launch_bounds__(256) void outproj_kernel(const float* __restrict__ h,
                                                      const float* __restrict__ Wout,
                                                      const float* __restrict__ bout,
                                                      float* __restrict__ out) {
    int warp = (blockIdx.x * blockDim.x + threadIdx.x) >> 5;
    if (warp >= NN) return;
    int lane = threadIdx.x & 31;
    float4 hv = *(const float4*)(h + (size_t)warp * HIDC + lane * 4);
    float4 wv = *(const float4*)(Wout + lane * 4);
    float a = hv.x * wv.x + hv.y * wv.y + hv.z * wv.z + hv.w * wv.w;
#pragma unroll
    for (int off = 16; off; off >>= 1) a += __shfl_xor_sync(0xffffffffu, a, off);
    if (lane == 0) out[warp] = a + bout[0];
}

// ---------------- launch ----------------
extern "C" void kernel_launch(void* const* d_in, const int* in_sizes, int n_in,
                              void* d_out, int out_size) {
    const float* x     = (const float*)d_in[0];
    const float* W_in  = (const float*)d_in[2];
    const float* b_in  = (const float*)d_in[3];
    const float* W_gcn = (const float*)d_in[4];
    const float* W_out = (const float*)d_in[5];
    const float* b_out = (const float*)d_in[6];
    const int*   ei    = (const int*)d_in[7];   // int32 words; dtype detected on device
    float* out = (float*)d_out;

    void *pDeg, *pH0, *pA, *pB, *pS;
    cudaGetSymbolAddress(&pDeg, g_deg);
    cudaGetSymbolAddress(&pH0,  g_h0);
    cudaGetSymbolAddress(&pA,   g_bufA);
    cudaGetSymbolAddress(&pB,   g_bufB);
    cudaGetSymbolAddress(&pS,   g_sbuf);
    float* h0   = (float*)pH0;
    float* bufA = (float*)pA;
    float* bufB = (float*)pB;
    float* sbuf = (float*)pS;

    // graph build
    detect_kernel<<<1, 32>>>(ei);
    cudaMemsetAsync(pDeg, 0, NN * sizeof(int), 0);
    count_kernel<<<EE / 256, 256>>>(ei);
    scan_kernel<<<1, 1024>>>();
    fill_kernel<<<EE / 256, 256>>>(ei);

    // input projection: h0 = x @ W_in + b_in
    gemm_kernel<<<NN / 32, 256>>>(x, W_in, b_in, 0.f, 1.f, 0, h0);

    const float* cur = h0;
    for (int i = 0; i < 8; i++) {
        spmm_kernel<<<NN / 8, 256>>>(cur, h0, sbuf);
        float beta = logf(0.5f / (float)(i + 1) + 1.0f);
        float* dst = (i & 1) ? bufB : bufA;
        gemm_kernel<<<NN / 32, 256>>>(sbuf, W_gcn + (size_t)i * HIDC * HIDC,
                                      nullptr, 1.0f - beta, beta, 1, dst);
        cur = dst;
    }

    outproj_kernel<<<NN / 8, 256>>>(cur, W_out, b_out, out);
}

// round 11
// speedup vs baseline: 1.5914x; 1.5914x over previous
#include <cuda_runtime.h>
#include <math.h>

#define NN 100000
#define EE 3200000
#define HIDC 128

// ---------------- device scratch (no allocations allowed) ----------------
__device__ int   g_flag64;          // 1 if edge_index is int64, 0 if int32
__device__ int   g_deg[NN];
__device__ float g_dinv[NN];
__device__ int   g_rowptr[NN + 1];
__device__ int   g_cursor[NN];
__device__ int   g_src[EE];
__device__ float g_w[EE];
__device__ float g_h0[(size_t)NN * HIDC];
__device__ float g_bufA[(size_t)NN * HIDC];
__device__ float g_bufB[(size_t)NN * HIDC];
__device__ float g_sbuf[(size_t)NN * HIDC];

// ---------------- f32x2 packed math helpers (sm_10x FFMA2) ----------------
__device__ __forceinline__ unsigned long long pk2(float a, float b) {
    unsigned long long r;
    asm("mov.b64 %0, {%1, %2};" : "=l"(r) : "f"(a), "f"(b));
    return r;
}
__device__ __forceinline__ void upk2(unsigned long long v, float& a, float& b) {
    asm("mov.b64 {%0, %1}, %2;" : "=f"(a), "=f"(b) : "l"(v));
}
__device__ __forceinline__ void fma2(unsigned long long& d,
                                     unsigned long long a,
                                     unsigned long long b) {
    asm("fma.rn.f32x2 %0, %1, %2, %0;" : "+l"(d) : "l"(a), "l"(b));
}

// ---------------- dtype detection ----------------
__global__ void detect_kernel(const int* __restrict__ ew) {
    if (threadIdx.x == 0) {
        int allzero = 1;
        for (int i = 0; i < 256; i++) {
            if (ew[2 * i + 1] != 0) { allzero = 0; break; }
        }
        g_flag64 = allzero;
    }
}

__device__ __forceinline__ int load_idx(const int* __restrict__ ew, long long elem, int f64) {
    return f64 ? ew[2 * elem] : ew[elem];   // little-endian low word
}

// ---------------- graph build ----------------
__global__ void count_kernel(const int* __restrict__ ew) {
    int e = blockIdx.x * blockDim.x + threadIdx.x;
    if (e < EE) {
        int f64 = g_flag64;
        int c = load_idx(ew, (long long)EE + e, f64);
        if ((unsigned)c < NN) atomicAdd(&g_deg[c], 1);
    }
}

__global__ void scan_kernel() {
    __shared__ int sums[1024];
    const int T = 1024;
    int t = threadIdx.x;
    const int CH = (NN + T - 1) / T;  // 98
    int lo = t * CH;
    int hi = lo + CH;
    if (hi > NN) hi = NN;
    if (lo > NN) lo = NN;
    int s = 0;
    for (int i = lo; i < hi; i++) s += g_deg[i];
    sums[t] = s;
    __syncthreads();
    for (int off = 1; off < T; off <<= 1) {
        int v = (t >= off) ? sums[t - off] : 0;
        __syncthreads();
        sums[t] += v;
        __syncthreads();
    }
    int run = sums[t] - s;
    for (int i = lo; i < hi; i++) {
        int d = g_deg[i];
        g_rowptr[i] = run;
        g_cursor[i] = run;
        g_dinv[i]   = rsqrtf((float)(d + 1));  // +1 self loop
        run += d;
    }
    if (t == T - 1) g_rowptr[NN] = run;
}

__global__ void fill_kernel(const int* __restrict__ ew) {
    int e = blockIdx.x * blockDim.x + threadIdx.x;
    if (e < EE) {
        int f64 = g_flag64;
        int r = load_idx(ew, e, f64);
        int c = load_idx(ew, (long long)EE + e, f64);
        if ((unsigned)r < NN && (unsigned)c < NN) {
            int pos = atomicAdd(&g_cursor[c], 1);
            g_src[pos] = r;
            g_w[pos]   = g_dinv[r] * g_dinv[c];
        }
    }
}

// ---------------- SpMM + residual: s = 0.9*(A_norm h) + 0.1*h0 ----------------
__global__ __launch_bounds__(256) void spmm_kernel(const float* __restrict__ h,
                                                   const float* __restrict__ h0f,
                                                   float* __restrict__ sout) {
    int warp = (blockIdx.x * blockDim.x + threadIdx.x) >> 5;
    if (warp >= NN) return;
    int lane = threadIdx.x & 31;
    int beg = g_rowptr[warp];
    int end = g_rowptr[warp + 1];

    float4 acc = make_float4(0.f, 0.f, 0.f, 0.f);
    int e0 = beg;
    for (; e0 + 32 <= end; e0 += 32) {
        int   src = g_src[e0 + lane];
        float w   = g_w[e0 + lane];
#pragma unroll 8
        for (int j = 0; j < 32; j++) {
            int   sidx = __shfl_sync(0xffffffffu, src, j);
            float ww   = __shfl_sync(0xffffffffu, w, j);
            float4 hv = *(const float4*)(h + (size_t)sidx * HIDC + lane * 4);
            acc.x = fmaf(ww, hv.x, acc.x);
            acc.y = fmaf(ww, hv.y, acc.y);
            acc.z = fmaf(ww, hv.z, acc.z);
            acc.w = fmaf(ww, hv.w, acc.w);
        }
    }
    if (e0 < end) {
        int cnt = end - e0;
        int   src = 0;
        float w   = 0.f;
        if (lane < cnt) { src = g_src[e0 + lane]; w = g_w[e0 + lane]; }
        for (int j = 0; j < cnt; j++) {
            int   sidx = __shfl_sync(0xffffffffu, src, j);
            float ww   = __shfl_sync(0xffffffffu, w, j);
            float4 hv = *(const float4*)(h + (size_t)sidx * HIDC + lane * 4);
            acc.x = fmaf(ww, hv.x, acc.x);
            acc.y = fmaf(ww, hv.y, acc.y);
            acc.z = fmaf(ww, hv.z, acc.z);
            acc.w = fmaf(ww, hv.w, acc.w);
        }
    }
    float di = g_dinv[warp];
    float ws = di * di;
    float4 hv = *(const float4*)(h + (size_t)warp * HIDC + lane * 4);
    acc.x = fmaf(ws, hv.x, acc.x);
    acc.y = fmaf(ws, hv.y, acc.y);
    acc.z = fmaf(ws, hv.z, acc.z);
    acc.w = fmaf(ws, hv.w, acc.w);

    float4 r0 = *(const float4*)(h0f + (size_t)warp * HIDC + lane * 4);
    float4 o;
    o.x = 0.9f * acc.x + 0.1f * r0.x;
    o.y = 0.9f * acc.y + 0.1f * r0.y;
    o.z = 0.9f * acc.z + 0.1f * r0.z;
    o.w = 0.9f * acc.w + 0.1f * r0.w;
    *(float4*)(sout + (size_t)warp * HIDC + lane * 4) = o;
}

// ---------------- GEMM: out = cs*S + cw*(S@W) (+bias) (relu?) ----------------
// Block tile: 64 rows x 128 cols, 256 threads (8 warps).
// Warp w -> rows w*8..w*8+7; lane -> cols lane*4..lane*4+3.
// Thread computes 8 rows x 4 cols with f32x2 packed FMA (16 u64 accumulators).
__global__ __launch_bounds__(256) void gemm_kernel(const float* __restrict__ S,
                                                   const float* __restrict__ W,
                                                   const float* __restrict__ bias,
                                                   float cs, float cw, int relu,
                                                   float* __restrict__ out) {
    __shared__ float ss[64][132];   // 132: float4-aligned row stride
    __shared__ float Ws[32][128];
    int tid  = threadIdx.x;
    int warp = tid >> 5;            // 0..7
    int lane = tid & 31;            // 0..31
    int row0 = blockIdx.x * 64;
    int rbase = warp * 8;

    // load S tile (coalesced, clamped rows)
    {
#pragma unroll
        for (int i = 0; i < 8; i++) {
            int idx = tid + i * 256;          // 0..2047
            int r = idx >> 5, c4 = idx & 31;
            int gr = row0 + r;
            if (gr > NN - 1) gr = NN - 1;
            float4 v = *(const float4*)(S + (size_t)gr * HIDC + c4 * 4);
            *(float4*)&ss[r][c4 * 4] = v;
        }
    }

    unsigned long long acc[8][2];
#pragma unroll
    for (int r = 0; r < 8; r++) { acc[r][0] = 0ull; acc[r][1] = 0ull; }

    for (int kc = 0; kc < 4; kc++) {
        __syncthreads();
        const float4* Wv = (const float4*)(W + (size_t)kc * 32 * HIDC);
#pragma unroll
        for (int i = 0; i < 4; i++) {
            int idx = tid + i * 256;
            int r = idx >> 5, c4 = idx & 31;
            *(float4*)&Ws[r][c4 * 4] = Wv[r * 32 + c4];
        }
        __syncthreads();

#pragma unroll
        for (int kk4 = 0; kk4 < 8; kk4++) {
            // W for 4 consecutive k, this thread's 4 cols -> packed pairs
            unsigned long long wp[4][2];
#pragma unroll
            for (int t = 0; t < 4; t++) {
                float4 w4 = *(const float4*)&Ws[kk4 * 4 + t][lane * 4];
                wp[t][0] = pk2(w4.x, w4.y);
                wp[t][1] = pk2(w4.z, w4.w);
            }
#pragma unroll
            for (int r = 0; r < 8; r++) {
                // 4 consecutive k values of S for this row (warp-broadcast LDS.128)
                float4 sv = *(const float4*)&ss[rbase + r][kc * 32 + kk4 * 4];
                unsigned long long s0 = pk2(sv.x, sv.x);
                unsigned long long s1 = pk2(sv.y, sv.y);
                unsigned long long s2 = pk2(sv.z, sv.z);
                unsigned long long s3 = pk2(sv.w, sv.w);
                fma2(acc[r][0], s0, wp[0][0]); fma2(acc[r][1], s0, wp[0][1]);
                fma2(acc[r][0], s1, wp[1][0]); fma2(acc[r][1], s1, wp[1][1]);
                fma2(acc[r][0], s2, wp[2][0]); fma2(acc[r][1], s2, wp[2][1]);
                fma2(acc[r][0], s3, wp[3][0]); fma2(acc[r][1], s3, wp[3][1]);
            }
        }
    }

    int col = lane * 4;
    float4 b4 = make_float4(0.f, 0.f, 0.f, 0.f);
    if (bias) b4 = *(const float4*)(bias + col);

#pragma unroll
    for (int r = 0; r < 8; r++) {
        int grow = row0 + rbase + r;
        if (grow >= NN) break;
        float4 o;
        upk2(acc[r][0], o.x, o.y);
        upk2(acc[r][1], o.z, o.w);
        o.x *= cw; o.y *= cw; o.z *= cw; o.w *= cw;
        if (cs != 0.f) {
            float4 sv = *(const float4*)&ss[rbase + r][col];
            o.x = fmaf(cs, sv.x, o.x);
            o.y = fmaf(cs, sv.y, o.y);
            o.z = fmaf(cs, sv.z, o.z);
            o.w = fmaf(cs, sv.w, o.w);
        }
        o.x += b4.x; o.y += b4.y; o.z += b4.z; o.w += b4.w;
        if (relu) {
            o.x = fmaxf(o.x, 0.f); o.y = fmaxf(o.y, 0.f);
            o.z = fmaxf(o.z, 0.f); o.w = fmaxf(o.w, 0.f);
        }
        *(float4*)(out + (size_t)grow * HIDC + col) = o;
    }
}

// ---------------- output projection ----------------
__global__ __launch_bounds__(256) void outproj_kernel(const float* __restrict__ h,
                                                      const float* __restrict__ Wout,
                                                      const float* __restrict__ bout,
                                                      float* __restrict__ out) {
    int warp = (blockIdx.x * blockDim.x + threadIdx.x) >> 5;
    if (warp >= NN) return;
    int lane = threadIdx.x & 31;
    float4 hv = *(const float4*)(h + (size_t)warp * HIDC + lane * 4);
    float4 wv = *(const float4*)(Wout + lane * 4);
    float a = hv.x * wv.x + hv.y * wv.y + hv.z * wv.z + hv.w * wv.w;
#pragma unroll
    for (int off = 16; off; off >>= 1) a += __shfl_xor_sync(0xffffffffu, a, off);
    if (lane == 0) out[warp] = a + bout[0];
}

// ---------------- launch ----------------
extern "C" void kernel_launch(void* const* d_in, const int* in_sizes, int n_in,
                              void* d_out, int out_size) {
    const float* x     = (const float*)d_in[0];
    const float* W_in  = (const float*)d_in[2];
    const float* b_in  = (const float*)d_in[3];
    const float* W_gcn = (const float*)d_in[4];
    const float* W_out = (const float*)d_in[5];
    const float* b_out = (const float*)d_in[6];
    const int*   ei    = (const int*)d_in[7];
    float* out = (float*)d_out;

    void *pDeg, *pH0, *pA, *pB, *pS;
    cudaGetSymbolAddress(&pDeg, g_deg);
    cudaGetSymbolAddress(&pH0,  g_h0);
    cudaGetSymbolAddress(&pA,   g_bufA);
    cudaGetSymbolAddress(&pB,   g_bufB);
    cudaGetSymbolAddress(&pS,   g_sbuf);
    float* h0   = (float*)pH0;
    float* bufA = (float*)pA;
    float* bufB = (float*)pB;
    float* sbuf = (float*)pS;

    // graph build
    detect_kernel<<<1, 32>>>(ei);
    cudaMemsetAsync(pDeg, 0, NN * sizeof(int), 0);
    count_kernel<<<EE / 256, 256>>>(ei);
    scan_kernel<<<1, 1024>>>();
    fill_kernel<<<EE / 256, 256>>>(ei);

    const int GB = (NN + 63) / 64;   // 1563 tiles of 64 rows

    // input projection: h0 = x @ W_in + b_in
    gemm_kernel<<<GB, 256>>>(x, W_in, b_in, 0.f, 1.f, 0, h0);

    const float* cur = h0;
    for (int i = 0; i < 8; i++) {
        spmm_kernel<<<NN / 8, 256>>>(cur, h0, sbuf);
        float beta = logf(0.5f / (float)(i + 1) + 1.0f);
        float* dst = (i & 1) ? bufB : bufA;
        gemm_kernel<<<GB, 256>>>(sbuf, W_gcn + (size_t)i * HIDC * HIDC,
                                 nullptr, 1.0f - beta, beta, 1, dst);
        cur = dst;
    }

    outproj_kernel<<<NN / 8, 256>>>(cur, W_out, b_out, out);
}

// round 12
// speedup vs baseline: 1.7764x; 1.1162x over previous
#include <cuda_runtime.h>
#include <cuda_fp16.h>
#include <math.h>

#define NN 100000
#define EE 3200000
#define HIDC 128

// ---------------- device scratch (no allocations allowed) ----------------
__device__ int    g_flag64;
__device__ int    g_deg[NN];
__device__ float  g_dinv[NN];
__device__ int    g_rowptr[NN + 1];
__device__ int    g_cursor[NN];
__device__ int    g_src[EE];
__device__ float  g_w[EE];
__device__ float  g_h0[(size_t)NN * HIDC];
__device__ float  g_bufA[(size_t)NN * HIDC];
__device__ float  g_bufB[(size_t)NN * HIDC];
__device__ float  g_sbuf[(size_t)NN * HIDC];
__device__ __half g_h16[(size_t)NN * HIDC];   // fp16 gather table

// ---------------- f32x2 packed math helpers (sm_10x FFMA2) ----------------
__device__ __forceinline__ unsigned long long pk2(float a, float b) {
    unsigned long long r;
    asm("mov.b64 %0, {%1, %2};" : "=l"(r) : "f"(a), "f"(b));
    return r;
}
__device__ __forceinline__ void upk2(unsigned long long v, float& a, float& b) {
    asm("mov.b64 {%0, %1}, %2;" : "=f"(a), "=f"(b) : "l"(v));
}
__device__ __forceinline__ void fma2(unsigned long long& d,
                                     unsigned long long a,
                                     unsigned long long b) {
    asm("fma.rn.f32x2 %0, %1, %2, %0;" : "+l"(d) : "l"(a), "l"(b));
}

// ---------------- dtype detection ----------------
__global__ void detect_kernel(const int* __restrict__ ew) {
    if (threadIdx.x == 0) {
        int allzero = 1;
        for (int i = 0; i < 256; i++) {
            if (ew[2 * i + 1] != 0) { allzero = 0; break; }
        }
        g_flag64 = allzero;
    }
}

__device__ __forceinline__ int load_idx(const int* __restrict__ ew, long long elem, int f64) {
    return f64 ? ew[2 * elem] : ew[elem];
}

// ---------------- graph build ----------------
__global__ void count_kernel(const int* __restrict__ ew) {
    int e = blockIdx.x * blockDim.x + threadIdx.x;
    if (e < EE) {
        int f64 = g_flag64;
        int c = load_idx(ew, (long long)EE + e, f64);
        if ((unsigned)c < NN) atomicAdd(&g_deg[c], 1);
    }
}

__global__ void scan_kernel() {
    __shared__ int sums[1024];
    const int T = 1024;
    int t = threadIdx.x;
    const int CH = (NN + T - 1) / T;
    int lo = t * CH;
    int hi = lo + CH;
    if (hi > NN) hi = NN;
    if (lo > NN) lo = NN;
    int s = 0;
    for (int i = lo; i < hi; i++) s += g_deg[i];
    sums[t] = s;
    __syncthreads();
    for (int off = 1; off < T; off <<= 1) {
        int v = (t >= off) ? sums[t - off] : 0;
        __syncthreads();
        sums[t] += v;
        __syncthreads();
    }
    int run = sums[t] - s;
    for (int i = lo; i < hi; i++) {
        int d = g_deg[i];
        g_rowptr[i] = run;
        g_cursor[i] = run;
        g_dinv[i]   = rsqrtf((float)(d + 1));
        run += d;
    }
    if (t == T - 1) g_rowptr[NN] = run;
}

__global__ void fill_kernel(const int* __restrict__ ew) {
    int e = blockIdx.x * blockDim.x + threadIdx.x;
    if (e < EE) {
        int f64 = g_flag64;
        int r = load_idx(ew, e, f64);
        int c = load_idx(ew, (long long)EE + e, f64);
        if ((unsigned)r < NN && (unsigned)c < NN) {
            int pos = atomicAdd(&g_cursor[c], 1);
            g_src[pos] = r;
            g_w[pos]   = g_dinv[r] * g_dinv[c];
        }
    }
}

// ---------------- SpMM + residual: s = 0.9*(A_norm h) + 0.1*h0 ----------------
// Gather path reads fp16 table (half traffic); self-loop + residual stay fp32.
__global__ __launch_bounds__(256) void spmm_kernel(const __half* __restrict__ h16,
                                                   const float* __restrict__ hf,
                                                   const float* __restrict__ h0f,
                                                   float* __restrict__ sout) {
    int warp = (blockIdx.x * blockDim.x + threadIdx.x) >> 5;
    if (warp >= NN) return;
    int lane = threadIdx.x & 31;
    int beg = g_rowptr[warp];
    int end = g_rowptr[warp + 1];

    float4 acc = make_float4(0.f, 0.f, 0.f, 0.f);
    int e0 = beg;
    for (; e0 + 32 <= end; e0 += 32) {
        int   src = g_src[e0 + lane];
        float w   = g_w[e0 + lane];
#pragma unroll 8
        for (int j = 0; j < 32; j++) {
            int   sidx = __shfl_sync(0xffffffffu, src, j);
            float ww   = __shfl_sync(0xffffffffu, w, j);
            uint2 rv = *(const uint2*)(h16 + (size_t)sidx * HIDC + lane * 4);
            float2 f0 = __half22float2(*(const __half2*)&rv.x);
            float2 f1 = __half22float2(*(const __half2*)&rv.y);
            acc.x = fmaf(ww, f0.x, acc.x);
            acc.y = fmaf(ww, f0.y, acc.y);
            acc.z = fmaf(ww, f1.x, acc.z);
            acc.w = fmaf(ww, f1.y, acc.w);
        }
    }
    if (e0 < end) {
        int cnt = end - e0;
        int   src = 0;
        float w   = 0.f;
        if (lane < cnt) { src = g_src[e0 + lane]; w = g_w[e0 + lane]; }
        for (int j = 0; j < cnt; j++) {
            int   sidx = __shfl_sync(0xffffffffu, src, j);
            float ww   = __shfl_sync(0xffffffffu, w, j);
            uint2 rv = *(const uint2*)(h16 + (size_t)sidx * HIDC + lane * 4);
            float2 f0 = __half22float2(*(const __half2*)&rv.x);
            float2 f1 = __half22float2(*(const __half2*)&rv.y);
            acc.x = fmaf(ww, f0.x, acc.x);
            acc.y = fmaf(ww, f0.y, acc.y);
            acc.z = fmaf(ww, f1.x, acc.z);
            acc.w = fmaf(ww, f1.y, acc.w);
        }
    }
    // self loop in fp32
    float di = g_dinv[warp];
    float ws = di * di;
    float4 hv = *(const float4*)(hf + (size_t)warp * HIDC + lane * 4);
    acc.x = fmaf(ws, hv.x, acc.x);
    acc.y = fmaf(ws, hv.y, acc.y);
    acc.z = fmaf(ws, hv.z, acc.z);
    acc.w = fmaf(ws, hv.w, acc.w);

    float4 r0 = *(const float4*)(h0f + (size_t)warp * HIDC + lane * 4);
    float4 o;
    o.x = 0.9f * acc.x + 0.1f * r0.x;
    o.y = 0.9f * acc.y + 0.1f * r0.y;
    o.z = 0.9f * acc.z + 0.1f * r0.z;
    o.w = 0.9f * acc.w + 0.1f * r0.w;
    *(float4*)(sout + (size_t)warp * HIDC + lane * 4) = o;
}

// ---------------- GEMM: out = cs*S + cw*(S@W) (+bias) (relu?) ----------------
// Also emits fp16 copy of the result into out16 (gather table for next SpMM).
__global__ __launch_bounds__(256) void gemm_kernel(const float* __restrict__ S,
                                                   const float* __restrict__ W,
                                                   const float* __restrict__ bias,
                                                   float cs, float cw, int relu,
                                                   float* __restrict__ out,
                                                   __half* __restrict__ out16) {
    __shared__ float ss[64][132];
    __shared__ float Ws[32][128];
    int tid  = threadIdx.x;
    int warp = tid >> 5;
    int lane = tid & 31;
    int row0 = blockIdx.x * 64;
    int rbase = warp * 8;

    {
#pragma unroll
        for (int i = 0; i < 8; i++) {
            int idx = tid + i * 256;
            int r = idx >> 5, c4 = idx & 31;
            int gr = row0 + r;
            if (gr > NN - 1) gr = NN - 1;
            float4 v = *(const float4*)(S + (size_t)gr * HIDC + c4 * 4);
            *(float4*)&ss[r][c4 * 4] = v;
        }
    }

    unsigned long long acc[8][2];
#pragma unroll
    for (int r = 0; r < 8; r++) { acc[r][0] = 0ull; acc[r][1] = 0ull; }

    for (int kc = 0; kc < 4; kc++) {
        __syncthreads();
        const float4* Wv = (const float4*)(W + (size_t)kc * 32 * HIDC);
#pragma unroll
        for (int i = 0; i < 4; i++) {
            int idx = tid + i * 256;
            int r = idx >> 5, c4 = idx & 31;
            *(float4*)&Ws[r][c4 * 4] = Wv[r * 32 + c4];
        }
        __syncthreads();

#pragma unroll
        for (int kk4 = 0; kk4 < 8; kk4++) {
            unsigned long long wp[4][2];
#pragma unroll
            for (int t = 0; t < 4; t++) {
                float4 w4 = *(const float4*)&Ws[kk4 * 4 + t][lane * 4];
                wp[t][0] = pk2(w4.x, w4.y);
                wp[t][1] = pk2(w4.z, w4.w);
            }
#pragma unroll
            for (int r = 0; r < 8; r++) {
                float4 sv = *(const float4*)&ss[rbase + r][kc * 32 + kk4 * 4];
                unsigned long long s0 = pk2(sv.x, sv.x);
                unsigned long long s1 = pk2(sv.y, sv.y);
                unsigned long long s2 = pk2(sv.z, sv.z);
                unsigned long long s3 = pk2(sv.w, sv.w);
                fma2(acc[r][0], s0, wp[0][0]); fma2(acc[r][1], s0, wp[0][1]);
                fma2(acc[r][0], s1, wp[1][0]); fma2(acc[r][1], s1, wp[1][1]);
                fma2(acc[r][0], s2, wp[2][0]); fma2(acc[r][1], s2, wp[2][1]);
                fma2(acc[r][0], s3, wp[3][0]); fma2(acc[r][1], s3, wp[3][1]);
            }
        }
    }

    int col = lane * 4;
    float4 b4 = make_float4(0.f, 0.f, 0.f, 0.f);
    if (bias) b4 = *(const float4*)(bias + col);

#pragma unroll
    for (int r = 0; r < 8; r++) {
        int grow = row0 + rbase + r;
        if (grow >= NN) break;
        float4 o;
        upk2(acc[r][0], o.x, o.y);
        upk2(acc[r][1], o.z, o.w);
        o.x *= cw; o.y *= cw; o.z *= cw; o.w *= cw;
        if (cs != 0.f) {
            float4 sv = *(const float4*)&ss[rbase + r][col];
            o.x = fmaf(cs, sv.x, o.x);
            o.y = fmaf(cs, sv.y, o.y);
            o.z = fmaf(cs, sv.z, o.z);
            o.w = fmaf(cs, sv.w, o.w);
        }
        o.x += b4.x; o.y += b4.y; o.z += b4.z; o.w += b4.w;
        if (relu) {
            o.x = fmaxf(o.x, 0.f); o.y = fmaxf(o.y, 0.f);
            o.z = fmaxf(o.z, 0.f); o.w = fmaxf(o.w, 0.f);
        }
        *(float4*)(out + (size_t)grow * HIDC + col) = o;
        if (out16) {
            uint2 hpack;
            *(__half2*)&hpack.x = __floats2half2_rn(o.x, o.y);
            *(__half2*)&hpack.y = __floats2half2_rn(o.z, o.w);
            *(uint2*)(out16 + (size_t)grow * HIDC + col) = hpack;
        }
    }
}

// ---------------- output projection ----------------
__global__ __launch_bounds__(256) void outproj_kernel(const float* __restrict__ h,
                                                      const float* __restrict__ Wout,
                                                      const float* __restrict__ bout,
                                                      float* __restrict__ out) {
    int warp = (blockIdx.x * blockDim.x + threadIdx.x) >> 5;
    if (warp >= NN) return;
    int lane = threadIdx.x & 31;
    float4 hv = *(const float4*)(h + (size_t)warp * HIDC + lane * 4);
    float4 wv = *(const float4*)(Wout + lane * 4);
    float a = hv.x * wv.x + hv.y * wv.y + hv.z * wv.z + hv.w * wv.w;
#pragma unroll
    for (int off = 16; off; off >>= 1) a += __shfl_xor_sync(0xffffffffu, a, off);
    if (lane == 0) out[warp] = a + bout[0];
}

// ---------------- launch ----------------
extern "C" void kernel_launch(void* const* d_in, const int* in_sizes, int n_in,
                              void* d_out, int out_size) {
    const float* x     = (const float*)d_in[0];
    const float* W_in  = (const float*)d_in[2];
    const float* b_in  = (const float*)d_in[3];
    const float* W_gcn = (const float*)d_in[4];
    const float* W_out = (const float*)d_in[5];
    const float* b_out = (const float*)d_in[6];
    const int*   ei    = (const int*)d_in[7];
    float* out = (float*)d_out;

    void *pDeg, *pH0, *pA, *pB, *pS, *pH16;
    cudaGetSymbolAddress(&pDeg, g_deg);
    cudaGetSymbolAddress(&pH0,  g_h0);
    cudaGetSymbolAddress(&pA,   g_bufA);
    cudaGetSymbolAddress(&pB,   g_bufB);
    cudaGetSymbolAddress(&pS,   g_sbuf);
    cudaGetSymbolAddress(&pH16, g_h16);
    float*  h0   = (float*)pH0;
    float*  bufA = (float*)pA;
    float*  bufB = (float*)pB;
    float*  sbuf = (float*)pS;
    __half* h16  = (__half*)pH16;

    // graph build
    detect_kernel<<<1, 32>>>(ei);
    cudaMemsetAsync(pDeg, 0, NN * sizeof(int), 0);
    count_kernel<<<EE / 256, 256>>>(ei);
    scan_kernel<<<1, 1024>>>();
    fill_kernel<<<EE / 256, 256>>>(ei);

    const int GB = (NN + 63) / 64;

    // input projection: h0 = x @ W_in + b_in (fp32 + fp16 table)
    gemm_kernel<<<GB, 256>>>(x, W_in, b_in, 0.f, 1.f, 0, h0, h16);

    const float* cur = h0;
    for (int i = 0; i < 8; i++) {
        spmm_kernel<<<NN / 8, 256>>>(h16, cur, h0, sbuf);
        float beta = logf(0.5f / (float)(i + 1) + 1.0f);
        float* dst = (i & 1) ? bufB : bufA;
        // last layer: no fp16 table needed (outproj reads fp32)
        __half* t16 = (i == 7) ? nullptr : h16;
        gemm_kernel<<<GB, 256>>>(sbuf, W_gcn + (size_t)i * HIDC * HIDC,
                                 nullptr, 1.0f - beta, beta, 1, dst, t16);
        cur = dst;
    }

    outproj_kernel<<<NN / 8, 256>>>(cur, W_out, b_out, out);
}